// round 5
// baseline (speedup 1.0000x reference)
#include <cuda_runtime.h>

#define B_  1024
#define I_  256
#define N_  512
#define D_  6
#define U_  16
#define L_  64
#define ND_ (N_ * D_)   // 3072

__device__ float g_W  [I_ * ND_];   // sparsemax(feature_selection_logits), [I][ND]
__device__ float g_FVt[ND_ * B_];   // feature values TRANSPOSED, [ND][B]
__device__ float g_sc [ND_];        // 0.5*exp(-lt)
__device__ float g_of [ND_];        // 0.5 - th*0.5*exp(-lt)

typedef unsigned long long u64;

__device__ __forceinline__ void fma2(u64 &acc, u64 a, u64 b) {
    asm("fma.rn.f32x2 %0, %1, %2, %0;" : "+l"(acc) : "l"(a), "l"(b));
}
__device__ __forceinline__ u64 pack2(float lo, float hi) {
    u64 r; asm("mov.b64 %0, {%1, %2};" : "=l"(r) : "f"(lo), "f"(hi)); return r;
}
__device__ __forceinline__ void unpack2(float &lo, float &hi, u64 v) {
    asm("mov.b64 {%0, %1}, %2;" : "=f"(lo), "=f"(hi) : "l"(v));
}
__device__ __forceinline__ u64 d2l(double d) { return __double_as_longlong(d); }

// ---------------------------------------------------------------------------
// Kernel A: sparsemax over last axis (D=6) for each (i, n)
// ---------------------------------------------------------------------------
__global__ void k_sparsemax(const float* __restrict__ fsl) {
    int idx = blockIdx.x * blockDim.x + threadIdx.x;
    if (idx >= I_ * N_) return;
    const float* z = fsl + (size_t)idx * D_;
    float z0 = z[0], z1 = z[1], z2 = z[2], z3 = z[3], z4 = z[4], z5 = z[5];
    float s0 = z0, s1 = z1, s2 = z2, s3 = z3, s4 = z4, s5 = z5;

#define CSWP(a, b) { float _mx = fmaxf(a, b); float _mn = fminf(a, b); a = _mx; b = _mn; }
    CSWP(s1, s2) CSWP(s4, s5) CSWP(s0, s2) CSWP(s3, s5)
    CSWP(s0, s1) CSWP(s3, s4) CSWP(s2, s5) CSWP(s0, s3)
    CSWP(s1, s4) CSWP(s2, s4) CSWP(s1, s3) CSWP(s2, s3)
#undef CSWP

    float cs = s0; int k = 1; float ts = cs;
    cs += s1; if (1.0f + 2.0f * s1 > cs) { k = 2; ts = cs; }
    cs += s2; if (1.0f + 3.0f * s2 > cs) { k = 3; ts = cs; }
    cs += s3; if (1.0f + 4.0f * s3 > cs) { k = 4; ts = cs; }
    cs += s4; if (1.0f + 5.0f * s4 > cs) { k = 5; ts = cs; }
    cs += s5; if (1.0f + 6.0f * s5 > cs) { k = 6; ts = cs; }
    float tau = (ts - 1.0f) / (float)k;

    float* w = g_W + (size_t)idx * D_;
    w[0] = fmaxf(z0 - tau, 0.0f);
    w[1] = fmaxf(z1 - tau, 0.0f);
    w[2] = fmaxf(z2 - tau, 0.0f);
    w[3] = fmaxf(z3 - tau, 0.0f);
    w[4] = fmaxf(z4 - tau, 0.0f);
    w[5] = fmaxf(z5 - tau, 0.0f);
}

__global__ void k_scaleoff(const float* __restrict__ th, const float* __restrict__ lt) {
    int idx = blockIdx.x * blockDim.x + threadIdx.x;
    if (idx >= ND_) return;
    float s = 0.5f * expf(-lt[idx]);
    g_sc[idx] = s;
    g_of[idx] = 0.5f - th[idx] * s;
}

// ---------------------------------------------------------------------------
// Kernel B: FVt[m=nd][j=b] = sum_k W[k][m] * x[j][k]
// M=3072 (nd), Ncols=1024 (b), K=256. Tile 128m x 64j, 256 thr, 8x4/thread.
// Register-prefetch double buffering over the 16 k-tiles.
// ---------------------------------------------------------------------------
__global__ void __launch_bounds__(256, 2) k_gemm(const float* __restrict__ x) {
    __shared__ float As[16][128];   // [k][m]
    __shared__ float Bs[16][68];    // [k][j], padded

    int t  = threadIdx.x;
    int tx = t & 15;        // j quad
    int ty = t >> 4;        // m oct
    int j0 = blockIdx.x * 64;
    int m0 = blockIdx.y * 128;

    int ak = t >> 4, amc = (t & 15) * 8;
    int bj = t >> 2, bkq = (t & 3) * 4;
    const float* aBase = g_W + (size_t)ak * ND_ + m0 + amc;
    const float* bBase = x + (size_t)(j0 + bj) * I_ + bkq;

    u64 acc2[4][4];
#pragma unroll
    for (int i = 0; i < 4; i++)
#pragma unroll
        for (int j = 0; j < 4; j++) acc2[i][j] = 0ull;

    float4 pa0 = *(const float4*)(aBase);
    float4 pa1 = *(const float4*)(aBase + 4);
    float4 pb  = *(const float4*)(bBase);

    for (int kt = 0; kt < I_; kt += 16) {
        *(float4*)&As[ak][amc]     = pa0;
        *(float4*)&As[ak][amc + 4] = pa1;
        Bs[bkq + 0][bj] = pb.x; Bs[bkq + 1][bj] = pb.y;
        Bs[bkq + 2][bj] = pb.z; Bs[bkq + 3][bj] = pb.w;
        __syncthreads();

        if (kt + 16 < I_) {
            pa0 = *(const float4*)(aBase + (size_t)(kt + 16) * ND_);
            pa1 = *(const float4*)(aBase + (size_t)(kt + 16) * ND_ + 4);
            pb  = *(const float4*)(bBase + kt + 16);
        }

#pragma unroll
        for (int kk = 0; kk < 16; kk++) {
            double2 a01 = *(const double2*)&As[kk][ty * 8];
            double2 a23 = *(const double2*)&As[kk][ty * 8 + 4];
            float4  bv  = *(const float4*)&Bs[kk][tx * 4];
            u64 am[4] = { d2l(a01.x), d2l(a01.y), d2l(a23.x), d2l(a23.y) };
            u64 bd[4] = { pack2(bv.x, bv.x), pack2(bv.y, bv.y),
                          pack2(bv.z, bv.z), pack2(bv.w, bv.w) };
#pragma unroll
            for (int mp = 0; mp < 4; mp++)
#pragma unroll
                for (int j = 0; j < 4; j++) fma2(acc2[mp][j], am[mp], bd[j]);
        }
        __syncthreads();
    }

#pragma unroll
    for (int mp = 0; mp < 4; mp++) {
        float lo0, hi0, lo1, hi1, lo2, hi2, lo3, hi3;
        unpack2(lo0, hi0, acc2[mp][0]);
        unpack2(lo1, hi1, acc2[mp][1]);
        unpack2(lo2, hi2, acc2[mp][2]);
        unpack2(lo3, hi3, acc2[mp][3]);
        int m = m0 + ty * 8 + mp * 2;
        *(float4*)(g_FVt + (size_t)m * B_ + j0 + tx * 4)       = make_float4(lo0, lo1, lo2, lo3);
        *(float4*)(g_FVt + (size_t)(m + 1) * B_ + j0 + tx * 4) = make_float4(hi0, hi1, hi2, hi3);
    }
}

// ---------------------------------------------------------------------------
// build the 16 leaf weights for quarter q (leaves q*16..q*16+15), packed pairs
// ---------------------------------------------------------------------------
__device__ __forceinline__ void leaf16(const float h[6], int q, u64 lp[8]) {
    float g0 = 1.0f - h[0], g1 = 1.0f - h[1], g2 = 1.0f - h[2], g3 = 1.0f - h[3];
    float f4 = (q & 1) ? (1.0f - h[4]) : h[4];
    float f5 = (q & 2) ? (1.0f - h[5]) : h[5];
    float pref = f4 * f5;
    float l1_0 = pref * h[0], l1_1 = pref * g0;
    float l2[4];
    l2[0] = l1_0 * h[1]; l2[1] = l1_1 * h[1];
    l2[2] = l1_0 * g1;   l2[3] = l1_1 * g1;
    float l3[8];
#pragma unroll
    for (int j = 0; j < 4; j++) { l3[j] = l2[j] * h[2]; l3[4 + j] = l2[j] * g2; }
    float l4[16];
#pragma unroll
    for (int j = 0; j < 8; j++) { l4[j] = l3[j] * h[3]; l4[8 + j] = l3[j] * g3; }
#pragma unroll
    for (int j = 0; j < 8; j++) lp[j] = pack2(l4[2 * j], l4[2 * j + 1]);
}

// ---------------------------------------------------------------------------
// Kernel C: one thread = TWO batch rows (b, b+64), EIGHT u's.
// Warps 0-1 handle u0-7, warps 2-3 handle u8-15 (uniform per warp -> broadcast).
// Every resp LDS.128 feeds 4 fma2. Acc dep distance = 8 fma2.
// Grid (8 b-groups of 128, 64 n-chunks of 8) = 512 blocks, 128 threads.
// ---------------------------------------------------------------------------
__global__ void __launch_bounds__(128, 4) k_forest(const float* __restrict__ resp,
                                                   float* __restrict__ out) {
    __shared__ float resp_s[U_][L_];   // [u][c]
    __shared__ float sc_s[48], of_s[48];

    int t   = threadIdx.x;
    int grp = t >> 6;          // 0: u 0-7, 1: u 8-15
    int bl  = t & 63;
    int bg  = blockIdx.x;      // 8 groups of 128 b
    int ng  = blockIdx.y;      // 64 chunks of 8 n
    int b0  = bg * 128 + bl;
    int b1  = b0 + 64;

    if (t < 48) { sc_s[t] = g_sc[ng * 48 + t]; of_s[t] = g_of[ng * 48 + t]; }
    __syncthreads();

    u64 acc[2][8];
#pragma unroll
    for (int r = 0; r < 2; r++)
#pragma unroll
        for (int j = 0; j < 8; j++) acc[r][j] = 0ull;

    for (int nl = 0; nl < 8; nl++) {
        int n = ng * 8 + nl;

        // sparsemoid bins for both rows — coalesced loads from FVt
        float h0[6], h1[6];
        const float* fvp = g_FVt + (size_t)n * 6 * B_;
#pragma unroll
        for (int d = 0; d < 6; d++) {
            float sc = sc_s[nl * 6 + d], of = of_s[nl * 6 + d];
            float v0 = fvp[(size_t)d * B_ + b0] * sc + of;
            float v1 = fvp[(size_t)d * B_ + b1] * sc + of;
            h0[d] = fminf(fmaxf(v0, 0.0f), 1.0f);
            h1[d] = fminf(fmaxf(v1, 0.0f), 1.0f);
        }

        __syncthreads();   // previous iteration's resp_s readers done
        {   // stage response[n]: 1024 floats, 2 float4/thread
            const float4* src = (const float4*)(resp + (size_t)n * (U_ * L_));
            float4* dst = (float4*)&resp_s[0][0];
            dst[t]       = src[t];
            dst[t + 128] = src[t + 128];
        }
        __syncthreads();

#pragma unroll
        for (int q = 0; q < 4; q++) {
            u64 lp0[8], lp1[8];
            leaf16(h0, q, lp0);
            leaf16(h1, q, lp1);

#pragma unroll
            for (int iup = 0; iup < 4; iup++) {
                int ua = (grp << 3) + iup;             // this warp's u, and u+4
                const double2* ra = (const double2*)&resp_s[ua][q * 16];
                const double2* rb = (const double2*)&resp_s[ua + 4][q * 16];
#pragma unroll
                for (int j4 = 0; j4 < 4; j4++) {
                    double2 va = ra[j4];               // broadcast LDS.128
                    double2 vb = rb[j4];
                    u64 ax = d2l(va.x), ay = d2l(va.y);
                    u64 bx = d2l(vb.x), by = d2l(vb.y);
                    fma2(acc[0][iup],     lp0[2 * j4],     ax);
                    fma2(acc[1][iup],     lp1[2 * j4],     ax);
                    fma2(acc[0][iup + 4], lp0[2 * j4],     bx);
                    fma2(acc[1][iup + 4], lp1[2 * j4],     bx);
                    fma2(acc[0][iup],     lp0[2 * j4 + 1], ay);
                    fma2(acc[1][iup],     lp1[2 * j4 + 1], ay);
                    fma2(acc[0][iup + 4], lp0[2 * j4 + 1], by);
                    fma2(acc[1][iup + 4], lp1[2 * j4 + 1], by);
                }
            }
        }
    }

#pragma unroll
    for (int j = 0; j < 8; j++) {
        int u = (grp << 3) + j;
        float lo, hi;
        unpack2(lo, hi, acc[0][j]);
        atomicAdd(&out[b0 * U_ + u], lo + hi);
        unpack2(lo, hi, acc[1][j]);
        atomicAdd(&out[b1 * U_ + u], lo + hi);
    }
}

// ---------------------------------------------------------------------------
extern "C" void kernel_launch(void* const* d_in, const int* in_sizes, int n_in,
                              void* d_out, int out_size) {
    const float* x    = (const float*)d_in[0];  // [B, I]
    const float* fsl  = (const float*)d_in[1];  // [I, N, D]
    const float* th   = (const float*)d_in[2];  // [N, D]
    const float* lt   = (const float*)d_in[3];  // [N, D]
    const float* resp = (const float*)d_in[4];  // [N, U, 2^D]
    float* out = (float*)d_out;                 // [B, U]

    cudaMemsetAsync(out, 0, (size_t)B_ * U_ * sizeof(float), 0);

    k_sparsemax<<<(I_ * N_ + 255) / 256, 256>>>(fsl);
    k_scaleoff<<<(ND_ + 255) / 256, 256>>>(th, lt);
    k_gemm<<<dim3(B_ / 64, ND_ / 128), 256>>>(x);
    k_forest<<<dim3(B_ / 128, N_ / 8), 128>>>(resp, out);
}

// round 6
// speedup vs baseline: 1.5994x; 1.5994x over previous
#include <cuda_runtime.h>

#define B_  1024
#define I_  256
#define N_  512
#define D_  6
#define U_  16
#define L_  64
#define ND_ (N_ * D_)   // 3072

__device__ float g_W  [I_ * ND_];   // sparsemax(feature_selection_logits), [I][ND]
__device__ float g_FVt[ND_ * B_];   // feature values TRANSPOSED, [ND][B]
__device__ float g_sc [ND_];        // 0.5*exp(-lt)
__device__ float g_of [ND_];        // 0.5 - th*0.5*exp(-lt)

typedef unsigned long long u64;

__device__ __forceinline__ void fma2(u64 &acc, u64 a, u64 b) {
    asm("fma.rn.f32x2 %0, %1, %2, %0;" : "+l"(acc) : "l"(a), "l"(b));
}
__device__ __forceinline__ u64 pack2(float lo, float hi) {
    u64 r; asm("mov.b64 %0, {%1, %2};" : "=l"(r) : "f"(lo), "f"(hi)); return r;
}
__device__ __forceinline__ void unpack2(float &lo, float &hi, u64 v) {
    asm("mov.b64 {%0, %1}, %2;" : "=f"(lo), "=f"(hi) : "l"(v));
}
__device__ __forceinline__ u64 d2l(double d) { return __double_as_longlong(d); }

// ---------------------------------------------------------------------------
// Kernel A: sparsemax over last axis (D=6) for each (i, n)
// ---------------------------------------------------------------------------
__global__ void k_sparsemax(const float* __restrict__ fsl) {
    int idx = blockIdx.x * blockDim.x + threadIdx.x;
    if (idx >= I_ * N_) return;
    const float* z = fsl + (size_t)idx * D_;
    float z0 = z[0], z1 = z[1], z2 = z[2], z3 = z[3], z4 = z[4], z5 = z[5];
    float s0 = z0, s1 = z1, s2 = z2, s3 = z3, s4 = z4, s5 = z5;

#define CSWP(a, b) { float _mx = fmaxf(a, b); float _mn = fminf(a, b); a = _mx; b = _mn; }
    CSWP(s1, s2) CSWP(s4, s5) CSWP(s0, s2) CSWP(s3, s5)
    CSWP(s0, s1) CSWP(s3, s4) CSWP(s2, s5) CSWP(s0, s3)
    CSWP(s1, s4) CSWP(s2, s4) CSWP(s1, s3) CSWP(s2, s3)
#undef CSWP

    float cs = s0; int k = 1; float ts = cs;
    cs += s1; if (1.0f + 2.0f * s1 > cs) { k = 2; ts = cs; }
    cs += s2; if (1.0f + 3.0f * s2 > cs) { k = 3; ts = cs; }
    cs += s3; if (1.0f + 4.0f * s3 > cs) { k = 4; ts = cs; }
    cs += s4; if (1.0f + 5.0f * s4 > cs) { k = 5; ts = cs; }
    cs += s5; if (1.0f + 6.0f * s5 > cs) { k = 6; ts = cs; }
    float tau = (ts - 1.0f) / (float)k;

    float* w = g_W + (size_t)idx * D_;
    w[0] = fmaxf(z0 - tau, 0.0f);
    w[1] = fmaxf(z1 - tau, 0.0f);
    w[2] = fmaxf(z2 - tau, 0.0f);
    w[3] = fmaxf(z3 - tau, 0.0f);
    w[4] = fmaxf(z4 - tau, 0.0f);
    w[5] = fmaxf(z5 - tau, 0.0f);
}

__global__ void k_scaleoff(const float* __restrict__ th, const float* __restrict__ lt) {
    int idx = blockIdx.x * blockDim.x + threadIdx.x;
    if (idx >= ND_) return;
    float s = 0.5f * expf(-lt[idx]);
    g_sc[idx] = s;
    g_of[idx] = 0.5f - th[idx] * s;
}

// ---------------------------------------------------------------------------
// Kernel B: FVt[m=nd][j=b] = sum_k W[k][m] * x[j][k]  (unchanged from R4)
// ---------------------------------------------------------------------------
__global__ void __launch_bounds__(256, 2) k_gemm(const float* __restrict__ x) {
    __shared__ float As[16][128];   // [k][m]
    __shared__ float Bs[16][68];    // [k][j], padded

    int t  = threadIdx.x;
    int tx = t & 15;
    int ty = t >> 4;
    int j0 = blockIdx.x * 64;
    int m0 = blockIdx.y * 128;

    int ak = t >> 4, amc = (t & 15) * 8;
    int bj = t >> 2, bkq = (t & 3) * 4;
    const float* aBase = g_W + (size_t)ak * ND_ + m0 + amc;
    const float* bBase = x + (size_t)(j0 + bj) * I_ + bkq;

    u64 acc2[4][4];
#pragma unroll
    for (int i = 0; i < 4; i++)
#pragma unroll
        for (int j = 0; j < 4; j++) acc2[i][j] = 0ull;

    float4 pa0 = *(const float4*)(aBase);
    float4 pa1 = *(const float4*)(aBase + 4);
    float4 pb  = *(const float4*)(bBase);

    for (int kt = 0; kt < I_; kt += 16) {
        *(float4*)&As[ak][amc]     = pa0;
        *(float4*)&As[ak][amc + 4] = pa1;
        Bs[bkq + 0][bj] = pb.x; Bs[bkq + 1][bj] = pb.y;
        Bs[bkq + 2][bj] = pb.z; Bs[bkq + 3][bj] = pb.w;
        __syncthreads();

        if (kt + 16 < I_) {
            pa0 = *(const float4*)(aBase + (size_t)(kt + 16) * ND_);
            pa1 = *(const float4*)(aBase + (size_t)(kt + 16) * ND_ + 4);
            pb  = *(const float4*)(bBase + kt + 16);
        }

#pragma unroll
        for (int kk = 0; kk < 16; kk++) {
            double2 a01 = *(const double2*)&As[kk][ty * 8];
            double2 a23 = *(const double2*)&As[kk][ty * 8 + 4];
            float4  bv  = *(const float4*)&Bs[kk][tx * 4];
            u64 am[4] = { d2l(a01.x), d2l(a01.y), d2l(a23.x), d2l(a23.y) };
            u64 bd[4] = { pack2(bv.x, bv.x), pack2(bv.y, bv.y),
                          pack2(bv.z, bv.z), pack2(bv.w, bv.w) };
#pragma unroll
            for (int mp = 0; mp < 4; mp++)
#pragma unroll
                for (int j = 0; j < 4; j++) fma2(acc2[mp][j], am[mp], bd[j]);
        }
        __syncthreads();
    }

#pragma unroll
    for (int mp = 0; mp < 4; mp++) {
        float lo0, hi0, lo1, hi1, lo2, hi2, lo3, hi3;
        unpack2(lo0, hi0, acc2[mp][0]);
        unpack2(lo1, hi1, acc2[mp][1]);
        unpack2(lo2, hi2, acc2[mp][2]);
        unpack2(lo3, hi3, acc2[mp][3]);
        int m = m0 + ty * 8 + mp * 2;
        *(float4*)(g_FVt + (size_t)m * B_ + j0 + tx * 4)       = make_float4(lo0, lo1, lo2, lo3);
        *(float4*)(g_FVt + (size_t)(m + 1) * B_ + j0 + tx * 4) = make_float4(hi0, hi1, hi2, hi3);
    }
}

// ---------------------------------------------------------------------------
// 8 leaf weights (bits 0-2 free; bit3=half, bits 4-5=q), packed into 4 pairs
// ---------------------------------------------------------------------------
__device__ __forceinline__ void leaf8(const float h[6], int q, int half, u64 lp[4]) {
    float f3 = half    ? (1.0f - h[3]) : h[3];
    float f4 = (q & 1) ? (1.0f - h[4]) : h[4];
    float f5 = (q & 2) ? (1.0f - h[5]) : h[5];
    float pref = f4 * f5 * f3;
    float g0 = 1.0f - h[0], g1 = 1.0f - h[1], g2 = 1.0f - h[2];
    float l1_0 = pref * h[0], l1_1 = pref * g0;
    float l2_0 = l1_0 * h[1], l2_1 = l1_1 * h[1];
    float l2_2 = l1_0 * g1,   l2_3 = l1_1 * g1;
    lp[0] = pack2(l2_0 * h[2], l2_1 * h[2]);
    lp[1] = pack2(l2_2 * h[2], l2_3 * h[2]);
    lp[2] = pack2(l2_0 * g2,   l2_1 * g2);
    lp[3] = pack2(l2_2 * g2,   l2_3 * g2);
}

// ---------------------------------------------------------------------------
// Kernel C: thread = 2 batch rows (b, b+64) x 8 u's. Register-lean:
// leaves processed in 8-leaf halves so only lp0[4]+lp1[4] are live.
// Grid (8 b-groups of 128, 128 n-chunks of 4) = 1024 blocks, 128 threads.
// ---------------------------------------------------------------------------
__global__ void __launch_bounds__(128, 5) k_forest(const float* __restrict__ resp,
                                                   float* __restrict__ out) {
    __shared__ float resp_s[U_][L_];   // [u][c]
    __shared__ float sc_s[24], of_s[24];

    int t   = threadIdx.x;
    int grp = t >> 6;          // 0: u 0-7, 1: u 8-15
    int bl  = t & 63;
    int bg  = blockIdx.x;      // 8 groups of 128 b
    int ng  = blockIdx.y;      // 128 chunks of 4 n
    int b0  = bg * 128 + bl;
    int b1  = b0 + 64;

    if (t < 24) { sc_s[t] = g_sc[ng * 24 + t]; of_s[t] = g_of[ng * 24 + t]; }
    __syncthreads();

    u64 acc[2][8];
#pragma unroll
    for (int r = 0; r < 2; r++)
#pragma unroll
        for (int j = 0; j < 8; j++) acc[r][j] = 0ull;

    for (int nl = 0; nl < 4; nl++) {
        int n = ng * 4 + nl;

        // sparsemoid bins for both rows — coalesced loads from FVt
        float h0[6], h1[6];
        const float* fvp = g_FVt + (size_t)n * 6 * B_;
#pragma unroll
        for (int d = 0; d < 6; d++) {
            float sc = sc_s[nl * 6 + d], of = of_s[nl * 6 + d];
            float v0 = fvp[(size_t)d * B_ + b0] * sc + of;
            float v1 = fvp[(size_t)d * B_ + b1] * sc + of;
            h0[d] = fminf(fmaxf(v0, 0.0f), 1.0f);
            h1[d] = fminf(fmaxf(v1, 0.0f), 1.0f);
        }

        __syncthreads();   // previous iteration's resp_s readers done
        {   // stage response[n]: 1024 floats, 2 float4/thread
            const float4* src = (const float4*)(resp + (size_t)n * (U_ * L_));
            float4* dst = (float4*)&resp_s[0][0];
            dst[t]       = src[t];
            dst[t + 128] = src[t + 128];
        }
        __syncthreads();

#pragma unroll
        for (int q = 0; q < 4; q++) {
#pragma unroll
            for (int half = 0; half < 2; half++) {
                u64 lp0[4], lp1[4];
                leaf8(h0, q, half, lp0);
                leaf8(h1, q, half, lp1);
                int cb = q * 16 + half * 8;

#pragma unroll
                for (int iup = 0; iup < 4; iup++) {
                    int ua = (grp << 3) + iup;
                    const double2* ra = (const double2*)&resp_s[ua][cb];
                    const double2* rb = (const double2*)&resp_s[ua + 4][cb];
                    double2 va0 = ra[0], va1 = ra[1];      // broadcast LDS.128
                    double2 vb0 = rb[0], vb1 = rb[1];
                    u64 a0 = d2l(va0.x), a1 = d2l(va0.y), a2 = d2l(va1.x), a3 = d2l(va1.y);
                    u64 c0 = d2l(vb0.x), c1 = d2l(vb0.y), c2 = d2l(vb1.x), c3 = d2l(vb1.y);
                    fma2(acc[0][iup],     lp0[0], a0);
                    fma2(acc[1][iup],     lp1[0], a0);
                    fma2(acc[0][iup + 4], lp0[0], c0);
                    fma2(acc[1][iup + 4], lp1[0], c0);
                    fma2(acc[0][iup],     lp0[1], a1);
                    fma2(acc[1][iup],     lp1[1], a1);
                    fma2(acc[0][iup + 4], lp0[1], c1);
                    fma2(acc[1][iup + 4], lp1[1], c1);
                    fma2(acc[0][iup],     lp0[2], a2);
                    fma2(acc[1][iup],     lp1[2], a2);
                    fma2(acc[0][iup + 4], lp0[2], c2);
                    fma2(acc[1][iup + 4], lp1[2], c2);
                    fma2(acc[0][iup],     lp0[3], a3);
                    fma2(acc[1][iup],     lp1[3], a3);
                    fma2(acc[0][iup + 4], lp0[3], c3);
                    fma2(acc[1][iup + 4], lp1[3], c3);
                }
            }
        }
    }

#pragma unroll
    for (int j = 0; j < 8; j++) {
        int u = (grp << 3) + j;
        float lo, hi;
        unpack2(lo, hi, acc[0][j]);
        atomicAdd(&out[b0 * U_ + u], lo + hi);
        unpack2(lo, hi, acc[1][j]);
        atomicAdd(&out[b1 * U_ + u], lo + hi);
    }
}

// ---------------------------------------------------------------------------
extern "C" void kernel_launch(void* const* d_in, const int* in_sizes, int n_in,
                              void* d_out, int out_size) {
    const float* x    = (const float*)d_in[0];  // [B, I]
    const float* fsl  = (const float*)d_in[1];  // [I, N, D]
    const float* th   = (const float*)d_in[2];  // [N, D]
    const float* lt   = (const float*)d_in[3];  // [N, D]
    const float* resp = (const float*)d_in[4];  // [N, U, 2^D]
    float* out = (float*)d_out;                 // [B, U]

    cudaMemsetAsync(out, 0, (size_t)B_ * U_ * sizeof(float), 0);

    k_sparsemax<<<(I_ * N_ + 255) / 256, 256>>>(fsl);
    k_scaleoff<<<(ND_ + 255) / 256, 256>>>(th, lt);
    k_gemm<<<dim3(B_ / 64, ND_ / 128), 256>>>(x);
    k_forest<<<dim3(B_ / 128, N_ / 4), 128>>>(resp, out);
}